// round 13
// baseline (speedup 1.0000x reference)
#include <cuda_runtime.h>
#include <math.h>

#define TQ 256
#define BQ 1024
#define DQ 64
#define HQ 32

// Scratch (no runtime allocation allowed)
__device__ float g_xt[TQ * BQ * HQ];                  // conv output, [t][b][o]
__device__ __align__(16) float g_w0t[192 * 32];       // vec4 layout, see prep
__device__ __align__(16) float g_w1t[96 * 32];
__device__ __align__(16) float g_w2t[96 * 32];
__device__ float g_hs[BQ * HQ];                       // persisted h between rec kernels
__device__ float g_cs[BQ * HQ];                       // persisted c

__device__ __forceinline__ float rcp_(float x) {
    float r; asm("rcp.approx.f32 %0, %1;" : "=f"(r) : "f"(x)); return r;
}
__device__ __forceinline__ float sigm_(float x) {
    return rcp_(1.0f + __expf(-x));
}
__device__ __forceinline__ float tanh_(float x) {
    return 1.0f - 2.0f * rcp_(1.0f + __expf(2.0f * x));
}
__device__ __forceinline__ float sigmoid_acc(float x) {
    return 1.0f / (1.0f + expf(-x));
}
__device__ __forceinline__ void fma2_(unsigned long long& acc,
                                      unsigned long long a,
                                      unsigned long long b) {
    asm("fma.rn.f32x2 %0, %1, %2, %3;" : "=l"(acc) : "l"(a), "l"(b), "l"(acc));
}
__device__ __forceinline__ float unpack_add_(unsigned long long acc) {
    float lo, hi;
    asm("mov.b64 {%0, %1}, %2;" : "=f"(lo), "=f"(hi) : "l"(acc));
    return lo + hi;
}
__device__ __forceinline__ unsigned long long pack2_(float lo, float hi) {
    unsigned long long r;
    asm("mov.b64 %0, {%1, %2};" : "=l"(r) : "f"(lo), "f"(hi));
    return r;
}

// ---------------------------------------------------------------------------
// Kernel 0: repack conv weights (unchanged).
// ---------------------------------------------------------------------------
__global__ void prep_kernel(const float* __restrict__ w0,
                            const float* __restrict__ w1,
                            const float* __restrict__ w2) {
    int i = threadIdx.x + blockIdx.x * 256;
    if (i < 6144) {
        int jj = i & 3, o = (i >> 2) & 31, kd4 = i >> 7;
        int k = kd4 >> 4, d4 = kd4 & 15;
        g_w0t[i] = w0[o * 192 + (4 * d4 + jj) * 3 + k];
    }
    if (i < 3072) {
        int jj = i & 3, o = (i >> 2) & 31, ki4 = i >> 7;
        int k = ki4 >> 3, i4 = ki4 & 7;
        g_w1t[i] = w1[o * 96 + (4 * i4 + jj) * 3 + k];
        g_w2t[i] = w2[o * 96 + (4 * i4 + jj) * 3 + k];
    }
}

// ---------------------------------------------------------------------------
// Conv row-group, computes NR rows and IMMEDIATELY stores (relu + time mask)
// to dst (or global for layer 2). Deep row blocking (NR=8/9) flips the
// L1:FFMA balance: 3 weight LDG.128 amortize over NR rows.
// ---------------------------------------------------------------------------
template <int NR, int ND4>
__device__ __forceinline__ void conv_group_store(
    const ulonglong2* __restrict__ wp, const ulonglong2* sv,
    int base, int o, float bz, float* dst, int trow0, int tlo, int thi) {
    unsigned long long acc[NR];
    #pragma unroll
    for (int r = 0; r < NR; r++) acc[r] = 0ull;
    #pragma unroll
    for (int d4 = 0; d4 < ND4; d4++) {
        ulonglong2 wk0 = __ldg(&wp[d4 * 32 + o]);
        ulonglong2 wk1 = __ldg(&wp[(ND4 + d4) * 32 + o]);
        ulonglong2 wk2 = __ldg(&wp[(2 * ND4 + d4) * 32 + o]);
        ulonglong2 rr[NR + 2];
        #pragma unroll
        for (int r = 0; r < NR + 2; r++) rr[r] = sv[(base + r) * ND4 + d4];
        #pragma unroll
        for (int r = 0; r < NR; r++) {
            fma2_(acc[r], wk0.x, rr[r].x);     fma2_(acc[r], wk0.y, rr[r].y);
            fma2_(acc[r], wk1.x, rr[r + 1].x); fma2_(acc[r], wk1.y, rr[r + 1].y);
            fma2_(acc[r], wk2.x, rr[r + 2].x); fma2_(acc[r], wk2.y, rr[r + 2].y);
        }
    }
    #pragma unroll
    for (int r = 0; r < NR; r++) {
        float v = fmaxf(unpack_add_(acc[r]) + bz, 0.0f);
        int tt = trow0 + r;
        if (tt < tlo || tt >= thi) v = 0.0f;
        dst[(base + r) * 32 + o] = v;
    }
}

// Layer-2 variant: stores to g_xt (always in range).
template <int NR, int ND4>
__device__ __forceinline__ void conv_group_out(
    const ulonglong2* __restrict__ wp, const ulonglong2* sv,
    int base, int o, float bz, float* gout, int t0, int b) {
    unsigned long long acc[NR];
    #pragma unroll
    for (int r = 0; r < NR; r++) acc[r] = 0ull;
    #pragma unroll
    for (int d4 = 0; d4 < ND4; d4++) {
        ulonglong2 wk0 = __ldg(&wp[d4 * 32 + o]);
        ulonglong2 wk1 = __ldg(&wp[(ND4 + d4) * 32 + o]);
        ulonglong2 wk2 = __ldg(&wp[(2 * ND4 + d4) * 32 + o]);
        ulonglong2 rr[NR + 2];
        #pragma unroll
        for (int r = 0; r < NR + 2; r++) rr[r] = sv[(base + r) * ND4 + d4];
        #pragma unroll
        for (int r = 0; r < NR; r++) {
            fma2_(acc[r], wk0.x, rr[r].x);     fma2_(acc[r], wk0.y, rr[r].y);
            fma2_(acc[r], wk1.x, rr[r + 1].x); fma2_(acc[r], wk1.y, rr[r + 1].y);
            fma2_(acc[r], wk2.x, rr[r + 2].x); fma2_(acc[r], wk2.y, rr[r + 2].y);
        }
    }
    #pragma unroll
    for (int r = 0; r < NR; r++) {
        const int t = t0 + base + r;
        gout[t * (BQ * HQ) + b * HQ + o] = fmaxf(unpack_add_(acc[r]) + bz, 0.0f);
    }
}

// ---------------------------------------------------------------------------
// Kernel 1: fused 3-layer TCN. 128 thr, 4 blocks/SM; 8+9 row groups.
// ---------------------------------------------------------------------------
__global__ __launch_bounds__(128, 4) void conv_fused_kernel(
    const float* __restrict__ x,
    const float* __restrict__ b0, const float* __restrict__ b1,
    const float* __restrict__ b2) {
    __shared__ __align__(16) float xs[70 * 64];
    __shared__ __align__(16) float s1[72 * 32];
    __shared__ __align__(16) float s2[68 * 32];
    const ulonglong2* xs2 = (const ulonglong2*)xs;
    const ulonglong2* s1v = (const ulonglong2*)s1;
    const ulonglong2* s2v = (const ulonglong2*)s2;

    const int tid = threadIdx.x;
    const int b = blockIdx.x >> 2;
    const int t0 = (blockIdx.x & 3) * 64;

    {
        float4* xs4f = (float4*)xs;
        const float4 zero4 = make_float4(0.f, 0.f, 0.f, 0.f);
        for (int i = tid; i < 70 * 16; i += 128) {
            int r = i >> 4, d4 = i & 15, t = t0 - 3 + r;
            xs4f[i] = (t >= 0 && t < TQ)
                ? __ldg((const float4*)(x + b * TQ * DQ + t * DQ + d4 * 4))
                : zero4;
        }
    }
    s1[68 * 32 + tid] = 0.0f;
    __syncthreads();

    const int w = tid >> 5, o = tid & 31;
    const ulonglong2* wp0 = (const ulonglong2*)g_w0t;
    const ulonglong2* wp1 = (const ulonglong2*)g_w1t;
    const ulonglong2* wp2 = (const ulonglong2*)g_w2t;

    const int rbase = 17 * w;

    // ---- layer 0: s1 row r <-> time t0-2+r ----
    {
        float bz = __ldg(&b0[o]);
        conv_group_store<8, 16>(wp0, xs2, rbase, o, bz, s1,
                                t0 - 2 + rbase, 0, TQ);
        conv_group_store<9, 16>(wp0, xs2, rbase + 8, o, bz, s1,
                                t0 - 2 + rbase + 8, 0, TQ);
    }
    __syncthreads();

    // ---- layer 1: s2 row r <-> time t0-1+r ----
    {
        float bz = __ldg(&b1[o]);
        conv_group_store<8, 8>(wp1, s1v, rbase, o, bz, s2,
                               t0 - 1 + rbase, 0, TQ);
        conv_group_store<9, 8>(wp1, s1v, rbase + 8, o, bz, s2,
                               t0 - 1 + rbase + 8, 0, TQ);
    }
    __syncthreads();

    // ---- layer 2: 16 rows per warp -> global ----
    {
        float bz = __ldg(&b2[o]);
        conv_group_out<8, 8>(wp2, s2v, 16 * w, o, bz, g_xt, t0, b);
        conv_group_out<8, 8>(wp2, s2v, 16 * w + 8, o, bz, g_xt, t0, b);
    }
}

// ---------------------------------------------------------------------------
// Conjugated RY gate (scalar, R7/R10 — measured best).
// ---------------------------------------------------------------------------
#define QGATE(MREG, LAM, G) do { \
    float b0r_ = (MREG) ? a1r : a0r; \
    float b0i_ = (MREG) ? a1i : a0i; \
    float b1r_ = (MREG) ? a0r : a1r; \
    float b1i_ = (MREG) ? a0i : a1i; \
    float o0r_ = __shfl_xor_sync(FULL, b0r_, (LAM)); \
    float o0i_ = __shfl_xor_sync(FULL, b0i_, (LAM)); \
    float o1r_ = __shfl_xor_sync(FULL, b1r_, (LAM)); \
    float o1i_ = __shfl_xor_sync(FULL, b1i_, (LAM)); \
    a0r = fmaf(gs0[G], o0r_, gc[G] * a0r); \
    a0i = fmaf(gs0[G], o0i_, gc[G] * a0i); \
    a1r = fmaf(gs1[G], o1r_, gc[G] * a1r); \
    a1i = fmaf(gs1[G], o1i_, gc[G] * a1i); \
} while (0)

// ---------------------------------------------------------------------------
// Kernel 2: recurrent scan over [TSTART, TEND) — exact R10 (best measured).
// ---------------------------------------------------------------------------
template <int TSTART, int TEND>
__global__ __launch_bounds__(256, 1) void recurrent_kernel(
    const float* __restrict__ Wih, const float* __restrict__ Whh,
    const float* __restrict__ bih, const float* __restrict__ bhh,
    const float* __restrict__ qweights,
    const float* __restrict__ Wfc, const float* __restrict__ bfc,
    const float* __restrict__ Wout, const float* __restrict__ boutp,
    float* __restrict__ out) {
    __shared__ __align__(16) float xhf[2][256];     // [half][b*64 + idx]
    __shared__ float gsm[2][128 * 5];               // [half][j*5 + bb]
    __shared__ float qc[18], qs[18];

    const unsigned FULL = 0xffffffffu;
    const int tid = threadIdx.x;
    const int l = tid & 31;
    const int wrp = tid >> 5;
    const int half = tid >> 7;
    const int wb = wrp & 3;
    const int bglob = blockIdx.x * 8 + wrp;
    const int j = tid & 127;
    const int barid = half + 1;

    // ---- pack weight column j as adjacent-k pairs ----
    unsigned long long wpk[32];
    #pragma unroll
    for (int p = 0; p < 16; p++)
        wpk[p] = pack2_(Wih[j * 32 + 2 * p], Wih[j * 32 + 2 * p + 1]);
    #pragma unroll
    for (int p = 0; p < 16; p++)
        wpk[16 + p] = pack2_(Whh[j * 32 + 2 * p], Whh[j * 32 + 2 * p + 1]);
    const float biasj = bih[j] + bhh[j];

    if (tid < 18) {
        float a = 0.5f * qweights[tid];
        qc[tid] = cosf(a);
        qs[tid] = sinf(a);
    }

    const float wfc0 = Wfc[l * 6 + 0], wfc1 = Wfc[l * 6 + 1], wfc2 = Wfc[l * 6 + 2];
    const float wfc3 = Wfc[l * 6 + 3], wfc4 = Wfc[l * 6 + 4], wfc5 = Wfc[l * 6 + 5];
    const float bfcl = bfc[l];
    const float woutl = Wout[l];
    __syncthreads();   // qc/qs visible

    // ---- layer-1 RY coefficients (folded into kets) ----
    float c1q[6], s1q[6];
    #pragma unroll
    for (int q = 0; q < 6; q++) { c1q[q] = qc[q]; s1q[q] = qs[q]; }

    // ---- conjugated-gate coefficients ----
    const int PHI[12]  = {31, 16, 24, 28, 30, 31, 21, 15, 23, 11, 21, 10};
    const int GREG[12] = { 0,  1,  1,  1,  1,  1,  1,  1,  0,  1,  0,  1};
    float gc[12], gs0[12], gs1[12];
    #pragma unroll
    for (int g = 0; g < 12; g++) {
        const int idx = 6 + g;
        float cg = qc[idx], sg = qs[idx];
        int f0 = __popc(l & PHI[g]) & 1;
        gc[g] = cg;
        gs0[g] = f0 ? sg : -sg;
        gs1[g] = (f0 ^ GREG[g]) ? sg : -sg;
    }

    float h, c;
    if (TSTART == 0) {
        h = 0.0f; c = 0.0f;
    } else {
        h = g_hs[bglob * HQ + l];
        c = g_cs[bglob * HQ + l];
    }

    float xt = g_xt[TSTART * (BQ * HQ) + bglob * HQ + l];

    for (int t = TSTART; t < TEND; t++) {
        // ---- stage activations batch-major: [b*64 + k] ----
        xhf[half][wb * 64 + l] = xt;
        xhf[half][wb * 64 + 32 + l] = h;
        asm volatile("bar.sync %0, 128;" :: "r"(barid) : "memory");

        float xt_next = 0.0f;
        if (t + 1 < TQ) xt_next = g_xt[(t + 1) * (BQ * HQ) + bglob * HQ + l];

        // ---- matvec ----
        {
            unsigned long long a0 = 0ull, a1 = 0ull, a2 = 0ull, a3 = 0ull;
            const ulonglong2* xv = (const ulonglong2*)&xhf[half][0];
            #pragma unroll
            for (int kg = 0; kg < 16; kg++) {
                ulonglong2 x0 = xv[kg];
                ulonglong2 x1 = xv[16 + kg];
                ulonglong2 x2 = xv[32 + kg];
                ulonglong2 x3 = xv[48 + kg];
                fma2_(a0, wpk[2 * kg], x0.x); fma2_(a0, wpk[2 * kg + 1], x0.y);
                fma2_(a1, wpk[2 * kg], x1.x); fma2_(a1, wpk[2 * kg + 1], x1.y);
                fma2_(a2, wpk[2 * kg], x2.x); fma2_(a2, wpk[2 * kg + 1], x2.y);
                fma2_(a3, wpk[2 * kg], x3.x); fma2_(a3, wpk[2 * kg + 1], x3.y);
            }
            gsm[half][j * 5 + 0] = unpack_add_(a0) + biasj;
            gsm[half][j * 5 + 1] = unpack_add_(a1) + biasj;
            gsm[half][j * 5 + 2] = unpack_add_(a2) + biasj;
            gsm[half][j * 5 + 3] = unpack_add_(a3) + biasj;
        }
        asm volatile("bar.sync %0, 128;" :: "r"(barid) : "memory");

        // ---- LSTM cell + chaotic maps ----
        float gi = gsm[half][l * 5 + wb];
        float gf = gsm[half][(l + 32) * 5 + wb];
        float gg = gsm[half][(l + 64) * 5 + wb];
        float go = gsm[half][(l + 96) * 5 + wb];
        c = sigm_(gf) * c + sigm_(gi) * tanh_(gg);
        h = sigm_(go) * tanh_(c);
        h = 3.99f * h * (1.0f - h);
        float x0h = __shfl_sync(FULL, h, 0);
        float y0h = __shfl_sync(FULL, h, 1);
        if (l == 0) h = 1.0f - 1.4f * (x0h * x0h) + y0h;
        if (l == 1) h = 0.3f * x0h;

        // ---- 6-qubit circuit ----
        float ang = (l < 6) ? 0.5f * h : 0.0f;
        float ssin, scos;
        __sincosf(ang, &ssin, &scos);
        float cs[6], sn[6];
        #pragma unroll
        for (int q = 0; q < 6; q++) {
            cs[q] = __shfl_sync(FULL, scos, q);
            sn[q] = __shfl_sync(FULL, ssin, q);
        }
        // kets psi_i = RY(layer1) * RZ * RY * RX |0>
        float p0r[6], p0i[6], p1r[6], p1i[6];
        #pragma unroll
        for (int i = 0; i < 6; i++) {
            const int i1 = (i + 1) % 6, i2 = (i + 2) % 6;
            float cx = cs[i], sx = sn[i];
            float cy = cs[i1], sy = sn[i1];
            float cz = cs[i2], sz = sn[i2];
            float ur = cy * cx, ui = sy * sx;
            float vr = sy * cx, vi = -(cy * sx);
            float q0r = ur * cz + ui * sz;
            float q0i = ui * cz - ur * sz;
            float q1r = vr * cz - vi * sz;
            float q1i = vi * cz + vr * sz;
            float cv = c1q[i], sv = s1q[i];
            p0r[i] = cv * q0r - sv * q1r;
            p0i[i] = cv * q0i - sv * q1i;
            p1r[i] = sv * q0r + cv * q1r;
            p1i[i] = sv * q0i + cv * q1i;
        }
        // product state: factor over qubits 1..5 (lane bits), split qubit 0
        float cr = 1.0f, cii = 0.0f;
        #pragma unroll
        for (int q = 1; q < 6; q++) {
            int bit = (l >> (5 - q)) & 1;
            float fr = bit ? p1r[q] : p0r[q];
            float fi = bit ? p1i[q] : p0i[q];
            float nr = cr * fr - cii * fi;
            float ni = cr * fi + cii * fr;
            cr = nr; cii = ni;
        }
        float a0r = cr * p0r[0] - cii * p0i[0];
        float a0i = cr * p0i[0] + cii * p0r[0];
        float a1r = cr * p1r[0] - cii * p1i[0];
        float a1i = cr * p1i[0] + cii * p1r[0];

        // ---- conjugated variational gates (12 x 4 shfls, no CNOTs) ----
        QGATE(1, 16, 0);  QGATE(0, 24, 1);  QGATE(0, 12, 2);
        QGATE(0, 6, 3);   QGATE(0, 3, 4);   QGATE(1, 17, 5);
        QGATE(1, 8, 6);   QGATE(0, 20, 7);  QGATE(0, 10, 8);
        QGATE(0, 5, 9);   QGATE(1, 18, 10); QGATE(0, 25, 11);

        // ---- dual WHT measurement; CNOT perms absorbed into Walsh indices ----
        float pp = a0r * a0r + a0i * a0i;
        float pq = a1r * a1r + a1i * a1i;
        float u = pp + pq;
        float wv = pp - pq;
        #pragma unroll
        for (int bmask = 16; bmask >= 1; bmask >>= 1) {
            float ou = __shfl_xor_sync(FULL, u, bmask);
            u = (l & bmask) ? (ou - u) : (u + ou);
            float ow = __shfl_xor_sync(FULL, wv, bmask);
            wv = (l & bmask) ? (ow - wv) : (wv + ow);
        }
        float e0 = __shfl_sync(FULL, wv, 12);
        float e1 = __shfl_sync(FULL, u, 26);
        float e2 = __shfl_sync(FULL, u, 13);
        float e3 = __shfl_sync(FULL, wv, 6);
        float e4 = __shfl_sync(FULL, wv, 19);
        float e5 = __shfl_sync(FULL, u, 25);
        h = h + e0 * wfc0 + e1 * wfc1 + e2 * wfc2
              + e3 * wfc3 + e4 * wfc4 + e5 * wfc5 + bfcl;

        xt = xt_next;
    }

    if (TEND < TQ) {
        g_hs[bglob * HQ + l] = h;
        g_cs[bglob * HQ + l] = c;
    } else {
        float v = h * woutl;
        #pragma unroll
        for (int m = 16; m >= 1; m >>= 1) v += __shfl_xor_sync(FULL, v, m);
        if (l == 0) out[bglob] = sigmoid_acc(v + boutp[0]);
    }
}

// ---------------------------------------------------------------------------
extern "C" void kernel_launch(void* const* d_in, const int* in_sizes, int n_in,
                              void* d_out, int out_size) {
    const float* x   = (const float*)d_in[0];
    const float* w0  = (const float*)d_in[1];
    const float* b0  = (const float*)d_in[2];
    const float* w1  = (const float*)d_in[3];
    const float* b1  = (const float*)d_in[4];
    const float* w2  = (const float*)d_in[5];
    const float* b2  = (const float*)d_in[6];
    const float* Wih = (const float*)d_in[7];
    const float* Whh = (const float*)d_in[8];
    const float* bih = (const float*)d_in[9];
    const float* bhh = (const float*)d_in[10];
    const float* qw  = (const float*)d_in[11];
    const float* Wfc = (const float*)d_in[12];
    const float* bfc = (const float*)d_in[13];
    const float* Wout = (const float*)d_in[14];
    const float* bout = (const float*)d_in[15];
    float* out = (float*)d_out;

    prep_kernel<<<24, 256>>>(w0, w1, w2);
    conv_fused_kernel<<<BQ * 4, 128>>>(x, b0, b1, b2);
    recurrent_kernel<0, 128><<<BQ / 8, 256>>>(Wih, Whh, bih, bhh, qw, Wfc, bfc,
                                              Wout, bout, out);
    recurrent_kernel<128, 256><<<BQ / 8, 256>>>(Wih, Whh, bih, bhh, qw, Wfc, bfc,
                                                Wout, bout, out);
}

// round 14
// speedup vs baseline: 1.0641x; 1.0641x over previous
#include <cuda_runtime.h>
#include <math.h>

#define TQ 256
#define BQ 1024
#define DQ 64
#define HQ 32

// Scratch (no runtime allocation allowed)
__device__ float g_xt[TQ * BQ * HQ];                  // conv output, [t][b][o]
__device__ __align__(16) float g_w0t[192 * 32];       // vec4 layout, see prep
__device__ __align__(16) float g_w1t[96 * 32];
__device__ __align__(16) float g_w2t[96 * 32];

__device__ __forceinline__ float rcp_(float x) {
    float r; asm("rcp.approx.f32 %0, %1;" : "=f"(r) : "f"(x)); return r;
}
__device__ __forceinline__ float sigm_(float x) {
    return rcp_(1.0f + __expf(-x));
}
__device__ __forceinline__ float tanh_(float x) {
    return 1.0f - 2.0f * rcp_(1.0f + __expf(2.0f * x));
}
__device__ __forceinline__ float sigmoid_acc(float x) {
    return 1.0f / (1.0f + expf(-x));
}
__device__ __forceinline__ void fma2_(unsigned long long& acc,
                                      unsigned long long a,
                                      unsigned long long b) {
    asm("fma.rn.f32x2 %0, %1, %2, %3;" : "=l"(acc) : "l"(a), "l"(b), "l"(acc));
}
__device__ __forceinline__ float unpack_add_(unsigned long long acc) {
    float lo, hi;
    asm("mov.b64 {%0, %1}, %2;" : "=f"(lo), "=f"(hi) : "l"(acc));
    return lo + hi;
}
__device__ __forceinline__ unsigned long long pack2_(float lo, float hi) {
    unsigned long long r;
    asm("mov.b64 %0, {%1, %2};" : "=l"(r) : "f"(lo), "f"(hi));
    return r;
}

// ---------------------------------------------------------------------------
// Kernel 0: repack conv weights (unchanged).
// ---------------------------------------------------------------------------
__global__ void prep_kernel(const float* __restrict__ w0,
                            const float* __restrict__ w1,
                            const float* __restrict__ w2) {
    int i = threadIdx.x + blockIdx.x * 256;
    if (i < 6144) {
        int jj = i & 3, o = (i >> 2) & 31, kd4 = i >> 7;
        int k = kd4 >> 4, d4 = kd4 & 15;
        g_w0t[i] = w0[o * 192 + (4 * d4 + jj) * 3 + k];
    }
    if (i < 3072) {
        int jj = i & 3, o = (i >> 2) & 31, ki4 = i >> 7;
        int k = ki4 >> 3, i4 = ki4 & 7;
        g_w1t[i] = w1[o * 96 + (4 * i4 + jj) * 3 + k];
        g_w2t[i] = w2[o * 96 + (4 * i4 + jj) * 3 + k];
    }
}

// ---------------------------------------------------------------------------
// Generic conv row-group (R10 structure, av-array + store-after).
// ---------------------------------------------------------------------------
template <int NR, int ND4>
__device__ __forceinline__ void conv_group(
    const ulonglong2* __restrict__ wp, const ulonglong2* sv,
    int base, int o, float bz, float* av) {
    unsigned long long acc[NR];
    #pragma unroll
    for (int r = 0; r < NR; r++) acc[r] = 0ull;
    #pragma unroll
    for (int d4 = 0; d4 < ND4; d4++) {
        ulonglong2 wk0 = __ldg(&wp[d4 * 32 + o]);
        ulonglong2 wk1 = __ldg(&wp[(ND4 + d4) * 32 + o]);
        ulonglong2 wk2 = __ldg(&wp[(2 * ND4 + d4) * 32 + o]);
        ulonglong2 rr[NR + 2];
        #pragma unroll
        for (int r = 0; r < NR + 2; r++) rr[r] = sv[(base + r) * ND4 + d4];
        #pragma unroll
        for (int r = 0; r < NR; r++) {
            fma2_(acc[r], wk0.x, rr[r].x);     fma2_(acc[r], wk0.y, rr[r].y);
            fma2_(acc[r], wk1.x, rr[r + 1].x); fma2_(acc[r], wk1.y, rr[r + 1].y);
            fma2_(acc[r], wk2.x, rr[r + 2].x); fma2_(acc[r], wk2.y, rr[r + 2].y);
        }
    }
    #pragma unroll
    for (int r = 0; r < NR; r++) av[r] = unpack_add_(acc[r]) + bz;
}

// ---------------------------------------------------------------------------
// Kernel 1: fused 3-layer TCN. 128 thr, 4 blocks/SM (R10). Only change vs
// R10: group depth 4+4+4+5 -> 6+6+5 (layers 0-1) and 4x4 -> 6+6+4 (layer 2).
// ---------------------------------------------------------------------------
__global__ __launch_bounds__(128, 4) void conv_fused_kernel(
    const float* __restrict__ x,
    const float* __restrict__ b0, const float* __restrict__ b1,
    const float* __restrict__ b2) {
    __shared__ __align__(16) float xs[70 * 64];
    __shared__ __align__(16) float s1[72 * 32];
    __shared__ __align__(16) float s2[68 * 32];
    const ulonglong2* xs2 = (const ulonglong2*)xs;
    const ulonglong2* s1v = (const ulonglong2*)s1;
    const ulonglong2* s2v = (const ulonglong2*)s2;

    const int tid = threadIdx.x;
    const int b = blockIdx.x >> 2;
    const int t0 = (blockIdx.x & 3) * 64;

    {
        float4* xs4f = (float4*)xs;
        const float4 zero4 = make_float4(0.f, 0.f, 0.f, 0.f);
        for (int i = tid; i < 70 * 16; i += 128) {
            int r = i >> 4, d4 = i & 15, t = t0 - 3 + r;
            xs4f[i] = (t >= 0 && t < TQ)
                ? __ldg((const float4*)(x + b * TQ * DQ + t * DQ + d4 * 4))
                : zero4;
        }
    }
    s1[68 * 32 + tid] = 0.0f;
    __syncthreads();

    const int w = tid >> 5, o = tid & 31;
    const ulonglong2* wp0 = (const ulonglong2*)g_w0t;
    const ulonglong2* wp1 = (const ulonglong2*)g_w1t;
    const ulonglong2* wp2 = (const ulonglong2*)g_w2t;

    const int rbase = 17 * w;

    // ---- layer 0: rows rbase..rbase+16 (times t0-2+row) ----
    {
        float bz = __ldg(&b0[o]);
        float av[17];
        conv_group<6, 16>(wp0, xs2, rbase, o, bz, av);
        conv_group<6, 16>(wp0, xs2, rbase + 6, o, bz, av + 6);
        conv_group<5, 16>(wp0, xs2, rbase + 12, o, bz, av + 12);
        #pragma unroll
        for (int r = 0; r < 17; r++) {
            int row = rbase + r, tt = t0 - 2 + row;
            float v = fmaxf(av[r], 0.0f);
            if (tt < 0 || tt >= TQ) v = 0.0f;
            s1[row * 32 + o] = v;
        }
    }
    __syncthreads();

    // ---- layer 1: rows rbase..rbase+16 (times t0-1+row) ----
    {
        float bz = __ldg(&b1[o]);
        float av[17];
        conv_group<6, 8>(wp1, s1v, rbase, o, bz, av);
        conv_group<6, 8>(wp1, s1v, rbase + 6, o, bz, av + 6);
        conv_group<5, 8>(wp1, s1v, rbase + 12, o, bz, av + 12);
        #pragma unroll
        for (int r = 0; r < 17; r++) {
            int row = rbase + r, tt = t0 - 1 + row;
            float v = fmaxf(av[r], 0.0f);
            if (tt < 0 || tt >= TQ) v = 0.0f;
            s2[row * 32 + o] = v;
        }
    }
    __syncthreads();

    // ---- layer 2: 16 rows per warp -> global ----
    {
        float bz = __ldg(&b2[o]);
        float av[16];
        conv_group<6, 8>(wp2, s2v, 16 * w, o, bz, av);
        conv_group<6, 8>(wp2, s2v, 16 * w + 6, o, bz, av + 6);
        conv_group<4, 8>(wp2, s2v, 16 * w + 12, o, bz, av + 12);
        #pragma unroll
        for (int r = 0; r < 16; r++) {
            const int t = t0 + 16 * w + r;
            g_xt[t * (BQ * HQ) + b * HQ + o] = fmaxf(av[r], 0.0f);
        }
    }
}

// ---------------------------------------------------------------------------
// Conjugated RY gate (scalar, R7/R10 — measured best).
// ---------------------------------------------------------------------------
#define QGATE(MREG, LAM, G) do { \
    float b0r_ = (MREG) ? a1r : a0r; \
    float b0i_ = (MREG) ? a1i : a0i; \
    float b1r_ = (MREG) ? a0r : a1r; \
    float b1i_ = (MREG) ? a0i : a1i; \
    float o0r_ = __shfl_xor_sync(FULL, b0r_, (LAM)); \
    float o0i_ = __shfl_xor_sync(FULL, b0i_, (LAM)); \
    float o1r_ = __shfl_xor_sync(FULL, b1r_, (LAM)); \
    float o1i_ = __shfl_xor_sync(FULL, b1i_, (LAM)); \
    a0r = fmaf(gs0[G], o0r_, gc[G] * a0r); \
    a0i = fmaf(gs0[G], o0i_, gc[G] * a0i); \
    a1r = fmaf(gs1[G], o1r_, gc[G] * a1r); \
    a1i = fmaf(gs1[G], o1i_, gc[G] * a1i); \
} while (0)

// ---------------------------------------------------------------------------
// Kernel 2: recurrent scan, single merged launch t=0..255 (R10 body).
// ---------------------------------------------------------------------------
__global__ __launch_bounds__(256, 1) void recurrent_kernel(
    const float* __restrict__ Wih, const float* __restrict__ Whh,
    const float* __restrict__ bih, const float* __restrict__ bhh,
    const float* __restrict__ qweights,
    const float* __restrict__ Wfc, const float* __restrict__ bfc,
    const float* __restrict__ Wout, const float* __restrict__ boutp,
    float* __restrict__ out) {
    __shared__ __align__(16) float xhf[2][256];     // [half][b*64 + idx]
    __shared__ float gsm[2][128 * 5];               // [half][j*5 + bb]
    __shared__ float qc[18], qs[18];

    const unsigned FULL = 0xffffffffu;
    const int tid = threadIdx.x;
    const int l = tid & 31;
    const int wrp = tid >> 5;
    const int half = tid >> 7;
    const int wb = wrp & 3;
    const int bglob = blockIdx.x * 8 + wrp;
    const int j = tid & 127;
    const int barid = half + 1;

    // ---- pack weight column j as adjacent-k pairs ----
    unsigned long long wpk[32];
    #pragma unroll
    for (int p = 0; p < 16; p++)
        wpk[p] = pack2_(Wih[j * 32 + 2 * p], Wih[j * 32 + 2 * p + 1]);
    #pragma unroll
    for (int p = 0; p < 16; p++)
        wpk[16 + p] = pack2_(Whh[j * 32 + 2 * p], Whh[j * 32 + 2 * p + 1]);
    const float biasj = bih[j] + bhh[j];

    if (tid < 18) {
        float a = 0.5f * qweights[tid];
        qc[tid] = cosf(a);
        qs[tid] = sinf(a);
    }

    const float wfc0 = Wfc[l * 6 + 0], wfc1 = Wfc[l * 6 + 1], wfc2 = Wfc[l * 6 + 2];
    const float wfc3 = Wfc[l * 6 + 3], wfc4 = Wfc[l * 6 + 4], wfc5 = Wfc[l * 6 + 5];
    const float bfcl = bfc[l];
    const float woutl = Wout[l];
    __syncthreads();   // qc/qs visible

    // ---- layer-1 RY coefficients (folded into kets) ----
    float c1q[6], s1q[6];
    #pragma unroll
    for (int q = 0; q < 6; q++) { c1q[q] = qc[q]; s1q[q] = qs[q]; }

    // ---- conjugated-gate coefficients ----
    const int PHI[12]  = {31, 16, 24, 28, 30, 31, 21, 15, 23, 11, 21, 10};
    const int GREG[12] = { 0,  1,  1,  1,  1,  1,  1,  1,  0,  1,  0,  1};
    float gc[12], gs0[12], gs1[12];
    #pragma unroll
    for (int g = 0; g < 12; g++) {
        const int idx = 6 + g;
        float cg = qc[idx], sg = qs[idx];
        int f0 = __popc(l & PHI[g]) & 1;
        gc[g] = cg;
        gs0[g] = f0 ? sg : -sg;
        gs1[g] = (f0 ^ GREG[g]) ? sg : -sg;
    }

    float h = 0.0f, c = 0.0f;
    float xt = g_xt[bglob * HQ + l];

    for (int t = 0; t < TQ; t++) {
        // ---- stage activations batch-major: [b*64 + k] ----
        xhf[half][wb * 64 + l] = xt;
        xhf[half][wb * 64 + 32 + l] = h;
        asm volatile("bar.sync %0, 128;" :: "r"(barid) : "memory");

        float xt_next = 0.0f;
        if (t + 1 < TQ) xt_next = g_xt[(t + 1) * (BQ * HQ) + bglob * HQ + l];

        // ---- matvec ----
        {
            unsigned long long a0 = 0ull, a1 = 0ull, a2 = 0ull, a3 = 0ull;
            const ulonglong2* xv = (const ulonglong2*)&xhf[half][0];
            #pragma unroll
            for (int kg = 0; kg < 16; kg++) {
                ulonglong2 x0 = xv[kg];
                ulonglong2 x1 = xv[16 + kg];
                ulonglong2 x2 = xv[32 + kg];
                ulonglong2 x3 = xv[48 + kg];
                fma2_(a0, wpk[2 * kg], x0.x); fma2_(a0, wpk[2 * kg + 1], x0.y);
                fma2_(a1, wpk[2 * kg], x1.x); fma2_(a1, wpk[2 * kg + 1], x1.y);
                fma2_(a2, wpk[2 * kg], x2.x); fma2_(a2, wpk[2 * kg + 1], x2.y);
                fma2_(a3, wpk[2 * kg], x3.x); fma2_(a3, wpk[2 * kg + 1], x3.y);
            }
            gsm[half][j * 5 + 0] = unpack_add_(a0) + biasj;
            gsm[half][j * 5 + 1] = unpack_add_(a1) + biasj;
            gsm[half][j * 5 + 2] = unpack_add_(a2) + biasj;
            gsm[half][j * 5 + 3] = unpack_add_(a3) + biasj;
        }
        asm volatile("bar.sync %0, 128;" :: "r"(barid) : "memory");

        // ---- LSTM cell + chaotic maps ----
        float gi = gsm[half][l * 5 + wb];
        float gf = gsm[half][(l + 32) * 5 + wb];
        float gg = gsm[half][(l + 64) * 5 + wb];
        float go = gsm[half][(l + 96) * 5 + wb];
        c = sigm_(gf) * c + sigm_(gi) * tanh_(gg);
        h = sigm_(go) * tanh_(c);
        h = 3.99f * h * (1.0f - h);
        float x0h = __shfl_sync(FULL, h, 0);
        float y0h = __shfl_sync(FULL, h, 1);
        if (l == 0) h = 1.0f - 1.4f * (x0h * x0h) + y0h;
        if (l == 1) h = 0.3f * x0h;

        // ---- 6-qubit circuit ----
        float ang = (l < 6) ? 0.5f * h : 0.0f;
        float ssin, scos;
        __sincosf(ang, &ssin, &scos);
        float cs[6], sn[6];
        #pragma unroll
        for (int q = 0; q < 6; q++) {
            cs[q] = __shfl_sync(FULL, scos, q);
            sn[q] = __shfl_sync(FULL, ssin, q);
        }
        // kets psi_i = RY(layer1) * RZ * RY * RX |0>
        float p0r[6], p0i[6], p1r[6], p1i[6];
        #pragma unroll
        for (int i = 0; i < 6; i++) {
            const int i1 = (i + 1) % 6, i2 = (i + 2) % 6;
            float cx = cs[i], sx = sn[i];
            float cy = cs[i1], sy = sn[i1];
            float cz = cs[i2], sz = sn[i2];
            float ur = cy * cx, ui = sy * sx;
            float vr = sy * cx, vi = -(cy * sx);
            float q0r = ur * cz + ui * sz;
            float q0i = ui * cz - ur * sz;
            float q1r = vr * cz - vi * sz;
            float q1i = vi * cz + vr * sz;
            float cv = c1q[i], sv = s1q[i];
            p0r[i] = cv * q0r - sv * q1r;
            p0i[i] = cv * q0i - sv * q1i;
            p1r[i] = sv * q0r + cv * q1r;
            p1i[i] = sv * q0i + cv * q1i;
        }
        // product state: factor over qubits 1..5 (lane bits), split qubit 0
        float cr = 1.0f, cii = 0.0f;
        #pragma unroll
        for (int q = 1; q < 6; q++) {
            int bit = (l >> (5 - q)) & 1;
            float fr = bit ? p1r[q] : p0r[q];
            float fi = bit ? p1i[q] : p0i[q];
            float nr = cr * fr - cii * fi;
            float ni = cr * fi + cii * fr;
            cr = nr; cii = ni;
        }
        float a0r = cr * p0r[0] - cii * p0i[0];
        float a0i = cr * p0i[0] + cii * p0r[0];
        float a1r = cr * p1r[0] - cii * p1i[0];
        float a1i = cr * p1i[0] + cii * p1r[0];

        // ---- conjugated variational gates (12 x 4 shfls, no CNOTs) ----
        QGATE(1, 16, 0);  QGATE(0, 24, 1);  QGATE(0, 12, 2);
        QGATE(0, 6, 3);   QGATE(0, 3, 4);   QGATE(1, 17, 5);
        QGATE(1, 8, 6);   QGATE(0, 20, 7);  QGATE(0, 10, 8);
        QGATE(0, 5, 9);   QGATE(1, 18, 10); QGATE(0, 25, 11);

        // ---- dual WHT measurement; CNOT perms absorbed into Walsh indices ----
        float pp = a0r * a0r + a0i * a0i;
        float pq = a1r * a1r + a1i * a1i;
        float u = pp + pq;
        float wv = pp - pq;
        #pragma unroll
        for (int bmask = 16; bmask >= 1; bmask >>= 1) {
            float ou = __shfl_xor_sync(FULL, u, bmask);
            u = (l & bmask) ? (ou - u) : (u + ou);
            float ow = __shfl_xor_sync(FULL, wv, bmask);
            wv = (l & bmask) ? (ow - wv) : (wv + ow);
        }
        float e0 = __shfl_sync(FULL, wv, 12);
        float e1 = __shfl_sync(FULL, u, 26);
        float e2 = __shfl_sync(FULL, u, 13);
        float e3 = __shfl_sync(FULL, wv, 6);
        float e4 = __shfl_sync(FULL, wv, 19);
        float e5 = __shfl_sync(FULL, u, 25);
        h = h + e0 * wfc0 + e1 * wfc1 + e2 * wfc2
              + e3 * wfc3 + e4 * wfc4 + e5 * wfc5 + bfcl;

        xt = xt_next;
    }

    // ---- output: sigmoid(h @ Wout.T + bout) ----
    float v = h * woutl;
    #pragma unroll
    for (int m = 16; m >= 1; m >>= 1) v += __shfl_xor_sync(FULL, v, m);
    if (l == 0) out[bglob] = sigmoid_acc(v + boutp[0]);
}

// ---------------------------------------------------------------------------
extern "C" void kernel_launch(void* const* d_in, const int* in_sizes, int n_in,
                              void* d_out, int out_size) {
    const float* x   = (const float*)d_in[0];
    const float* w0  = (const float*)d_in[1];
    const float* b0  = (const float*)d_in[2];
    const float* w1  = (const float*)d_in[3];
    const float* b1  = (const float*)d_in[4];
    const float* w2  = (const float*)d_in[5];
    const float* b2  = (const float*)d_in[6];
    const float* Wih = (const float*)d_in[7];
    const float* Whh = (const float*)d_in[8];
    const float* bih = (const float*)d_in[9];
    const float* bhh = (const float*)d_in[10];
    const float* qw  = (const float*)d_in[11];
    const float* Wfc = (const float*)d_in[12];
    const float* bfc = (const float*)d_in[13];
    const float* Wout = (const float*)d_in[14];
    const float* bout = (const float*)d_in[15];
    float* out = (float*)d_out;

    prep_kernel<<<24, 256>>>(w0, w1, w2);
    conv_fused_kernel<<<BQ * 4, 128>>>(x, b0, b1, b2);
    recurrent_kernel<<<BQ / 8, 256>>>(Wih, Whh, bih, bhh, qw, Wfc, bfc,
                                      Wout, bout, out);
}

// round 15
// speedup vs baseline: 1.0865x; 1.0210x over previous
#include <cuda_runtime.h>
#include <math.h>

#define TQ 256
#define BQ 1024
#define DQ 64
#define HQ 32

// Scratch (no runtime allocation allowed)
__device__ float g_xt[TQ * BQ * HQ];                  // conv output, [t][b][o]
__device__ __align__(16) float g_w0t[192 * 32];       // vec4 layout, see prep
__device__ __align__(16) float g_w1t[96 * 32];
__device__ __align__(16) float g_w2t[96 * 32];

__device__ __forceinline__ float rcp_(float x) {
    float r; asm("rcp.approx.f32 %0, %1;" : "=f"(r) : "f"(x)); return r;
}
__device__ __forceinline__ float sigm_(float x) {
    return rcp_(1.0f + __expf(-x));
}
__device__ __forceinline__ float tanh_(float x) {
    return 1.0f - 2.0f * rcp_(1.0f + __expf(2.0f * x));
}
__device__ __forceinline__ float sigmoid_acc(float x) {
    return 1.0f / (1.0f + expf(-x));
}
__device__ __forceinline__ void fma2_(unsigned long long& acc,
                                      unsigned long long a,
                                      unsigned long long b) {
    asm("fma.rn.f32x2 %0, %1, %2, %3;" : "=l"(acc) : "l"(a), "l"(b), "l"(acc));
}
__device__ __forceinline__ float unpack_add_(unsigned long long acc) {
    float lo, hi;
    asm("mov.b64 {%0, %1}, %2;" : "=f"(lo), "=f"(hi) : "l"(acc));
    return lo + hi;
}
__device__ __forceinline__ unsigned long long pack2_(float lo, float hi) {
    unsigned long long r;
    asm("mov.b64 %0, {%1, %2};" : "=l"(r) : "f"(lo), "f"(hi));
    return r;
}

// ---------------------------------------------------------------------------
// Kernel 0: repack conv weights (unchanged).
// ---------------------------------------------------------------------------
__global__ void prep_kernel(const float* __restrict__ w0,
                            const float* __restrict__ w1,
                            const float* __restrict__ w2) {
    int i = threadIdx.x + blockIdx.x * 256;
    if (i < 6144) {
        int jj = i & 3, o = (i >> 2) & 31, kd4 = i >> 7;
        int k = kd4 >> 4, d4 = kd4 & 15;
        g_w0t[i] = w0[o * 192 + (4 * d4 + jj) * 3 + k];
    }
    if (i < 3072) {
        int jj = i & 3, o = (i >> 2) & 31, ki4 = i >> 7;
        int k = ki4 >> 3, i4 = ki4 & 7;
        g_w1t[i] = w1[o * 96 + (4 * i4 + jj) * 3 + k];
        g_w2t[i] = w2[o * 96 + (4 * i4 + jj) * 3 + k];
    }
}

// ---------------------------------------------------------------------------
// Generic conv row-group (R10/R13 structure, av-array + store-after).
// ---------------------------------------------------------------------------
template <int NR, int ND4>
__device__ __forceinline__ void conv_group(
    const ulonglong2* __restrict__ wp, const ulonglong2* sv,
    int base, int o, float bz, float* av) {
    unsigned long long acc[NR];
    #pragma unroll
    for (int r = 0; r < NR; r++) acc[r] = 0ull;
    #pragma unroll
    for (int d4 = 0; d4 < ND4; d4++) {
        ulonglong2 wk0 = __ldg(&wp[d4 * 32 + o]);
        ulonglong2 wk1 = __ldg(&wp[(ND4 + d4) * 32 + o]);
        ulonglong2 wk2 = __ldg(&wp[(2 * ND4 + d4) * 32 + o]);
        ulonglong2 rr[NR + 2];
        #pragma unroll
        for (int r = 0; r < NR + 2; r++) rr[r] = sv[(base + r) * ND4 + d4];
        #pragma unroll
        for (int r = 0; r < NR; r++) {
            fma2_(acc[r], wk0.x, rr[r].x);     fma2_(acc[r], wk0.y, rr[r].y);
            fma2_(acc[r], wk1.x, rr[r + 1].x); fma2_(acc[r], wk1.y, rr[r + 1].y);
            fma2_(acc[r], wk2.x, rr[r + 2].x); fma2_(acc[r], wk2.y, rr[r + 2].y);
        }
    }
    #pragma unroll
    for (int r = 0; r < NR; r++) av[r] = unpack_add_(acc[r]) + bz;
}

// ---------------------------------------------------------------------------
// Kernel 1: fused 3-layer TCN. 128 thr, 4 blocks/SM. Only change vs R13:
// group depth 6+6+5 -> 8+9 (layers 0-1), 6+6+4 -> 8+8 (layer 2).
// ---------------------------------------------------------------------------
__global__ __launch_bounds__(128, 4) void conv_fused_kernel(
    const float* __restrict__ x,
    const float* __restrict__ b0, const float* __restrict__ b1,
    const float* __restrict__ b2) {
    __shared__ __align__(16) float xs[70 * 64];
    __shared__ __align__(16) float s1[72 * 32];
    __shared__ __align__(16) float s2[68 * 32];
    const ulonglong2* xs2 = (const ulonglong2*)xs;
    const ulonglong2* s1v = (const ulonglong2*)s1;
    const ulonglong2* s2v = (const ulonglong2*)s2;

    const int tid = threadIdx.x;
    const int b = blockIdx.x >> 2;
    const int t0 = (blockIdx.x & 3) * 64;

    {
        float4* xs4f = (float4*)xs;
        const float4 zero4 = make_float4(0.f, 0.f, 0.f, 0.f);
        for (int i = tid; i < 70 * 16; i += 128) {
            int r = i >> 4, d4 = i & 15, t = t0 - 3 + r;
            xs4f[i] = (t >= 0 && t < TQ)
                ? __ldg((const float4*)(x + b * TQ * DQ + t * DQ + d4 * 4))
                : zero4;
        }
    }
    s1[68 * 32 + tid] = 0.0f;
    __syncthreads();

    const int w = tid >> 5, o = tid & 31;
    const ulonglong2* wp0 = (const ulonglong2*)g_w0t;
    const ulonglong2* wp1 = (const ulonglong2*)g_w1t;
    const ulonglong2* wp2 = (const ulonglong2*)g_w2t;

    const int rbase = 17 * w;

    // ---- layer 0: rows rbase..rbase+16 (times t0-2+row) ----
    {
        float bz = __ldg(&b0[o]);
        float av[17];
        conv_group<8, 16>(wp0, xs2, rbase, o, bz, av);
        conv_group<9, 16>(wp0, xs2, rbase + 8, o, bz, av + 8);
        #pragma unroll
        for (int r = 0; r < 17; r++) {
            int row = rbase + r, tt = t0 - 2 + row;
            float v = fmaxf(av[r], 0.0f);
            if (tt < 0 || tt >= TQ) v = 0.0f;
            s1[row * 32 + o] = v;
        }
    }
    __syncthreads();

    // ---- layer 1: rows rbase..rbase+16 (times t0-1+row) ----
    {
        float bz = __ldg(&b1[o]);
        float av[17];
        conv_group<8, 8>(wp1, s1v, rbase, o, bz, av);
        conv_group<9, 8>(wp1, s1v, rbase + 8, o, bz, av + 8);
        #pragma unroll
        for (int r = 0; r < 17; r++) {
            int row = rbase + r, tt = t0 - 1 + row;
            float v = fmaxf(av[r], 0.0f);
            if (tt < 0 || tt >= TQ) v = 0.0f;
            s2[row * 32 + o] = v;
        }
    }
    __syncthreads();

    // ---- layer 2: 16 rows per warp -> global ----
    {
        float bz = __ldg(&b2[o]);
        float av[16];
        conv_group<8, 8>(wp2, s2v, 16 * w, o, bz, av);
        conv_group<8, 8>(wp2, s2v, 16 * w + 8, o, bz, av + 8);
        #pragma unroll
        for (int r = 0; r < 16; r++) {
            const int t = t0 + 16 * w + r;
            g_xt[t * (BQ * HQ) + b * HQ + o] = fmaxf(av[r], 0.0f);
        }
    }
}

// ---------------------------------------------------------------------------
// Conjugated RY gate (scalar, R7/R10 — measured best).
// ---------------------------------------------------------------------------
#define QGATE(MREG, LAM, G) do { \
    float b0r_ = (MREG) ? a1r : a0r; \
    float b0i_ = (MREG) ? a1i : a0i; \
    float b1r_ = (MREG) ? a0r : a1r; \
    float b1i_ = (MREG) ? a0i : a1i; \
    float o0r_ = __shfl_xor_sync(FULL, b0r_, (LAM)); \
    float o0i_ = __shfl_xor_sync(FULL, b0i_, (LAM)); \
    float o1r_ = __shfl_xor_sync(FULL, b1r_, (LAM)); \
    float o1i_ = __shfl_xor_sync(FULL, b1i_, (LAM)); \
    a0r = fmaf(gs0[G], o0r_, gc[G] * a0r); \
    a0i = fmaf(gs0[G], o0i_, gc[G] * a0i); \
    a1r = fmaf(gs1[G], o1r_, gc[G] * a1r); \
    a1i = fmaf(gs1[G], o1i_, gc[G] * a1i); \
} while (0)

// ---------------------------------------------------------------------------
// Kernel 2: recurrent scan, single merged launch t=0..255 (R13, unchanged).
// ---------------------------------------------------------------------------
__global__ __launch_bounds__(256, 1) void recurrent_kernel(
    const float* __restrict__ Wih, const float* __restrict__ Whh,
    const float* __restrict__ bih, const float* __restrict__ bhh,
    const float* __restrict__ qweights,
    const float* __restrict__ Wfc, const float* __restrict__ bfc,
    const float* __restrict__ Wout, const float* __restrict__ boutp,
    float* __restrict__ out) {
    __shared__ __align__(16) float xhf[2][256];     // [half][b*64 + idx]
    __shared__ float gsm[2][128 * 5];               // [half][j*5 + bb]
    __shared__ float qc[18], qs[18];

    const unsigned FULL = 0xffffffffu;
    const int tid = threadIdx.x;
    const int l = tid & 31;
    const int wrp = tid >> 5;
    const int half = tid >> 7;
    const int wb = wrp & 3;
    const int bglob = blockIdx.x * 8 + wrp;
    const int j = tid & 127;
    const int barid = half + 1;

    // ---- pack weight column j as adjacent-k pairs ----
    unsigned long long wpk[32];
    #pragma unroll
    for (int p = 0; p < 16; p++)
        wpk[p] = pack2_(Wih[j * 32 + 2 * p], Wih[j * 32 + 2 * p + 1]);
    #pragma unroll
    for (int p = 0; p < 16; p++)
        wpk[16 + p] = pack2_(Whh[j * 32 + 2 * p], Whh[j * 32 + 2 * p + 1]);
    const float biasj = bih[j] + bhh[j];

    if (tid < 18) {
        float a = 0.5f * qweights[tid];
        qc[tid] = cosf(a);
        qs[tid] = sinf(a);
    }

    const float wfc0 = Wfc[l * 6 + 0], wfc1 = Wfc[l * 6 + 1], wfc2 = Wfc[l * 6 + 2];
    const float wfc3 = Wfc[l * 6 + 3], wfc4 = Wfc[l * 6 + 4], wfc5 = Wfc[l * 6 + 5];
    const float bfcl = bfc[l];
    const float woutl = Wout[l];
    __syncthreads();   // qc/qs visible

    // ---- layer-1 RY coefficients (folded into kets) ----
    float c1q[6], s1q[6];
    #pragma unroll
    for (int q = 0; q < 6; q++) { c1q[q] = qc[q]; s1q[q] = qs[q]; }

    // ---- conjugated-gate coefficients ----
    const int PHI[12]  = {31, 16, 24, 28, 30, 31, 21, 15, 23, 11, 21, 10};
    const int GREG[12] = { 0,  1,  1,  1,  1,  1,  1,  1,  0,  1,  0,  1};
    float gc[12], gs0[12], gs1[12];
    #pragma unroll
    for (int g = 0; g < 12; g++) {
        const int idx = 6 + g;
        float cg = qc[idx], sg = qs[idx];
        int f0 = __popc(l & PHI[g]) & 1;
        gc[g] = cg;
        gs0[g] = f0 ? sg : -sg;
        gs1[g] = (f0 ^ GREG[g]) ? sg : -sg;
    }

    float h = 0.0f, c = 0.0f;
    float xt = g_xt[bglob * HQ + l];

    for (int t = 0; t < TQ; t++) {
        // ---- stage activations batch-major: [b*64 + k] ----
        xhf[half][wb * 64 + l] = xt;
        xhf[half][wb * 64 + 32 + l] = h;
        asm volatile("bar.sync %0, 128;" :: "r"(barid) : "memory");

        float xt_next = 0.0f;
        if (t + 1 < TQ) xt_next = g_xt[(t + 1) * (BQ * HQ) + bglob * HQ + l];

        // ---- matvec ----
        {
            unsigned long long a0 = 0ull, a1 = 0ull, a2 = 0ull, a3 = 0ull;
            const ulonglong2* xv = (const ulonglong2*)&xhf[half][0];
            #pragma unroll
            for (int kg = 0; kg < 16; kg++) {
                ulonglong2 x0 = xv[kg];
                ulonglong2 x1 = xv[16 + kg];
                ulonglong2 x2 = xv[32 + kg];
                ulonglong2 x3 = xv[48 + kg];
                fma2_(a0, wpk[2 * kg], x0.x); fma2_(a0, wpk[2 * kg + 1], x0.y);
                fma2_(a1, wpk[2 * kg], x1.x); fma2_(a1, wpk[2 * kg + 1], x1.y);
                fma2_(a2, wpk[2 * kg], x2.x); fma2_(a2, wpk[2 * kg + 1], x2.y);
                fma2_(a3, wpk[2 * kg], x3.x); fma2_(a3, wpk[2 * kg + 1], x3.y);
            }
            gsm[half][j * 5 + 0] = unpack_add_(a0) + biasj;
            gsm[half][j * 5 + 1] = unpack_add_(a1) + biasj;
            gsm[half][j * 5 + 2] = unpack_add_(a2) + biasj;
            gsm[half][j * 5 + 3] = unpack_add_(a3) + biasj;
        }
        asm volatile("bar.sync %0, 128;" :: "r"(barid) : "memory");

        // ---- LSTM cell + chaotic maps ----
        float gi = gsm[half][l * 5 + wb];
        float gf = gsm[half][(l + 32) * 5 + wb];
        float gg = gsm[half][(l + 64) * 5 + wb];
        float go = gsm[half][(l + 96) * 5 + wb];
        c = sigm_(gf) * c + sigm_(gi) * tanh_(gg);
        h = sigm_(go) * tanh_(c);
        h = 3.99f * h * (1.0f - h);
        float x0h = __shfl_sync(FULL, h, 0);
        float y0h = __shfl_sync(FULL, h, 1);
        if (l == 0) h = 1.0f - 1.4f * (x0h * x0h) + y0h;
        if (l == 1) h = 0.3f * x0h;

        // ---- 6-qubit circuit ----
        float ang = (l < 6) ? 0.5f * h : 0.0f;
        float ssin, scos;
        __sincosf(ang, &ssin, &scos);
        float cs[6], sn[6];
        #pragma unroll
        for (int q = 0; q < 6; q++) {
            cs[q] = __shfl_sync(FULL, scos, q);
            sn[q] = __shfl_sync(FULL, ssin, q);
        }
        // kets psi_i = RY(layer1) * RZ * RY * RX |0>
        float p0r[6], p0i[6], p1r[6], p1i[6];
        #pragma unroll
        for (int i = 0; i < 6; i++) {
            const int i1 = (i + 1) % 6, i2 = (i + 2) % 6;
            float cx = cs[i], sx = sn[i];
            float cy = cs[i1], sy = sn[i1];
            float cz = cs[i2], sz = sn[i2];
            float ur = cy * cx, ui = sy * sx;
            float vr = sy * cx, vi = -(cy * sx);
            float q0r = ur * cz + ui * sz;
            float q0i = ui * cz - ur * sz;
            float q1r = vr * cz - vi * sz;
            float q1i = vi * cz + vr * sz;
            float cv = c1q[i], sv = s1q[i];
            p0r[i] = cv * q0r - sv * q1r;
            p0i[i] = cv * q0i - sv * q1i;
            p1r[i] = sv * q0r + cv * q1r;
            p1i[i] = sv * q0i + cv * q1i;
        }
        // product state: factor over qubits 1..5 (lane bits), split qubit 0
        float cr = 1.0f, cii = 0.0f;
        #pragma unroll
        for (int q = 1; q < 6; q++) {
            int bit = (l >> (5 - q)) & 1;
            float fr = bit ? p1r[q] : p0r[q];
            float fi = bit ? p1i[q] : p0i[q];
            float nr = cr * fr - cii * fi;
            float ni = cr * fi + cii * fr;
            cr = nr; cii = ni;
        }
        float a0r = cr * p0r[0] - cii * p0i[0];
        float a0i = cr * p0i[0] + cii * p0r[0];
        float a1r = cr * p1r[0] - cii * p1i[0];
        float a1i = cr * p1i[0] + cii * p1r[0];

        // ---- conjugated variational gates (12 x 4 shfls, no CNOTs) ----
        QGATE(1, 16, 0);  QGATE(0, 24, 1);  QGATE(0, 12, 2);
        QGATE(0, 6, 3);   QGATE(0, 3, 4);   QGATE(1, 17, 5);
        QGATE(1, 8, 6);   QGATE(0, 20, 7);  QGATE(0, 10, 8);
        QGATE(0, 5, 9);   QGATE(1, 18, 10); QGATE(0, 25, 11);

        // ---- dual WHT measurement; CNOT perms absorbed into Walsh indices ----
        float pp = a0r * a0r + a0i * a0i;
        float pq = a1r * a1r + a1i * a1i;
        float u = pp + pq;
        float wv = pp - pq;
        #pragma unroll
        for (int bmask = 16; bmask >= 1; bmask >>= 1) {
            float ou = __shfl_xor_sync(FULL, u, bmask);
            u = (l & bmask) ? (ou - u) : (u + ou);
            float ow = __shfl_xor_sync(FULL, wv, bmask);
            wv = (l & bmask) ? (ow - wv) : (wv + ow);
        }
        float e0 = __shfl_sync(FULL, wv, 12);
        float e1 = __shfl_sync(FULL, u, 26);
        float e2 = __shfl_sync(FULL, u, 13);
        float e3 = __shfl_sync(FULL, wv, 6);
        float e4 = __shfl_sync(FULL, wv, 19);
        float e5 = __shfl_sync(FULL, u, 25);
        h = h + e0 * wfc0 + e1 * wfc1 + e2 * wfc2
              + e3 * wfc3 + e4 * wfc4 + e5 * wfc5 + bfcl;

        xt = xt_next;
    }

    // ---- output: sigmoid(h @ Wout.T + bout) ----
    float v = h * woutl;
    #pragma unroll
    for (int m = 16; m >= 1; m >>= 1) v += __shfl_xor_sync(FULL, v, m);
    if (l == 0) out[bglob] = sigmoid_acc(v + boutp[0]);
}

// ---------------------------------------------------------------------------
extern "C" void kernel_launch(void* const* d_in, const int* in_sizes, int n_in,
                              void* d_out, int out_size) {
    const float* x   = (const float*)d_in[0];
    const float* w0  = (const float*)d_in[1];
    const float* b0  = (const float*)d_in[2];
    const float* w1  = (const float*)d_in[3];
    const float* b1  = (const float*)d_in[4];
    const float* w2  = (const float*)d_in[5];
    const float* b2  = (const float*)d_in[6];
    const float* Wih = (const float*)d_in[7];
    const float* Whh = (const float*)d_in[8];
    const float* bih = (const float*)d_in[9];
    const float* bhh = (const float*)d_in[10];
    const float* qw  = (const float*)d_in[11];
    const float* Wfc = (const float*)d_in[12];
    const float* bfc = (const float*)d_in[13];
    const float* Wout = (const float*)d_in[14];
    const float* bout = (const float*)d_in[15];
    float* out = (float*)d_out;

    prep_kernel<<<24, 256>>>(w0, w1, w2);
    conv_fused_kernel<<<BQ * 4, 128>>>(x, b0, b1, b2);
    recurrent_kernel<<<BQ / 8, 256>>>(Wih, Whh, bih, bhh, qw, Wfc, bfc,
                                      Wout, bout, out);
}